// round 15
// baseline (speedup 1.0000x reference)
#include <cuda_runtime.h>
#include <cuda_bf16.h>
#include <math.h>
#include <stdint.h>

// Problem constants (fixed by setup_inputs)
#define Bq   32
#define Sq   128
#define Cq   384
#define Hh   8
#define Ww   512
#define Nkv  (Hh*Ww)        // 4096
#define HD2  192            // head dim for nh=2 cross-attn
// SIGMA = 3 -> 2*sigma^2 = 18

// ---------------------------------------------------------------------------
// Scratch (single __device__ global; no allocations allowed)
// ---------------------------------------------------------------------------
#define SZ_BWC   (Bq*Ww*Cq)
#define SZ_BW2C  (Bq*Ww*2*Cq)
#define SZ_BSC   (Bq*Sq*Cq)
#define SZ_BS2C  (Bq*Sq*2*Cq)
#define SZ_SC1   (Bq*2*Sq*Sq)
#define SZ_SC2   (Bq*2*Sq*Ww)
#define SZ_SCM   (Bq*Sq*Ww)
#define SZ_PT    (Bq*Sq)

#define OFF_DECM   0
#define OFF_DEC    (OFF_DECM + SZ_BWC)
#define OFF_LNDEC  (OFF_DEC + SZ_BWC)
#define OFF_KVMAIN (OFF_LNDEC + SZ_BWC)
#define OFF_KV2    (OFF_KVMAIN + SZ_BW2C)
#define OFF_KV1    (OFF_KV2 + SZ_BW2C)
#define OFF_QH     (OFF_KV1 + SZ_BS2C)
#define OFF_P0     (OFF_QH   + SZ_BSC)
#define OFF_LNA    (OFF_P0   + SZ_BSC)
#define OFF_LNB    (OFF_LNA  + SZ_BSC)
#define OFF_QH1    (OFF_LNB  + SZ_BSC)
#define OFF_X1     (OFF_QH1  + SZ_BSC)
#define OFF_P1     (OFF_X1   + SZ_BSC)
#define OFF_QH2    (OFF_P1   + SZ_BSC)
#define OFF_X2     (OFF_QH2  + SZ_BSC)
#define OFF_P2     (OFF_X2   + SZ_BSC)
#define OFF_TBUF   (OFF_P2   + SZ_BSC)
#define OFF_XMAIN  (OFF_TBUF + SZ_BSC)
#define OFF_SC1    (OFF_XMAIN+ SZ_BSC)
#define OFF_SC2    (OFF_SC1  + SZ_SC1)
#define OFF_SCM    (OFF_SC2  + SZ_SC2)
#define OFF_PT     (OFF_SCM  + SZ_SCM)
#define SCR_TOTAL  (OFF_PT + SZ_PT)

__device__ float SCR[SCR_TOTAL];

// ---------------------------------------------------------------------------
// Block reductions
// ---------------------------------------------------------------------------
__device__ __forceinline__ float blk_reduce_sum(float v) {
    __shared__ float sh[32];
    int lane = threadIdx.x & 31, w = threadIdx.x >> 5;
    #pragma unroll
    for (int o = 16; o; o >>= 1) v += __shfl_xor_sync(0xffffffffu, v, o);
    __syncthreads();
    if (lane == 0) sh[w] = v;
    __syncthreads();
    int nw = (blockDim.x + 31) >> 5;
    float r = (lane < nw) ? sh[lane] : 0.f;
    #pragma unroll
    for (int o = 16; o; o >>= 1) r += __shfl_xor_sync(0xffffffffu, r, o);
    return r;
}

__device__ __forceinline__ float blk_reduce_max(float v) {
    __shared__ float sh[32];
    int lane = threadIdx.x & 31, w = threadIdx.x >> 5;
    #pragma unroll
    for (int o = 16; o; o >>= 1) v = fmaxf(v, __shfl_xor_sync(0xffffffffu, v, o));
    __syncthreads();
    if (lane == 0) sh[w] = v;
    __syncthreads();
    int nw = (blockDim.x + 31) >> 5;
    float r = (lane < nw) ? sh[lane] : -3.4e38f;
    #pragma unroll
    for (int o = 16; o; o >>= 1) r = fmaxf(r, __shfl_xor_sync(0xffffffffu, r, o));
    return r;
}

// ---------------------------------------------------------------------------
// tf32 helpers
// ---------------------------------------------------------------------------
__device__ __forceinline__ uint32_t f2tf32(float f) {
    uint32_t u;
    asm("cvt.rna.tf32.f32 %0, %1;" : "=r"(u) : "f"(f));
    return u;
}

#define MMA_TF32(c, a, b0_, b1_)                                              \
    asm("mma.sync.aligned.m16n8k8.row.col.f32.tf32.tf32.f32 "                 \
        "{%0,%1,%2,%3}, {%4,%5,%6,%7}, {%8,%9}, {%0,%1,%2,%3};"               \
        : "+f"((c)[0]), "+f"((c)[1]), "+f"((c)[2]), "+f"((c)[3])              \
        : "r"((a)[0]), "r"((a)[1]), "r"((a)[2]), "r"((a)[3]),                 \
          "r"(b0_), "r"(b1_))

#define LDSM_X4(r0, r1, r2, r3, addr)                                         \
    asm volatile("ldmatrix.sync.aligned.m8n8.x4.shared.b16 {%0,%1,%2,%3}, [%4];" \
        : "=r"(r0), "=r"(r1), "=r"(r2), "=r"(r3) : "r"(addr))

// B column permutation: n -> (n>>5)*32 + (n&7)*4 + ((n>>3)&3)
__device__ __forceinline__ int bpos(int n) {
    return ((n >> 5) << 5) + ((n & 7) << 2) + ((n >> 3) & 3);
}

// ---------------------------------------------------------------------------
// TF32 tensor-core GEMM: C = alpha * A @ op(B) (+ bias)
// Block BM x 64, THREADS = 2*BM (8 or 4 warps), warp tile 32x32,
// mma m16n8k8 (2 M-tiles x 4 N-tiles per warp), K-tile 16,
// register-prefetch double buffering.
// A smem: row-major [m][16k], stride 20 u32; A fragments via ldmatrix.x4
//   (row starts 20r mod 32 = perfect bank permutation -> conflict-free).
// B smem: [k][pos(n)], stride 72; each thread's 4 per-nt fragment words are
//   contiguous -> one LDS.128 per (k8, reg). Chunk bank-group (2*tig+g)%8 is
//   distinct within each quarter-warp -> conflict-free 4-wavefront LDS.128.
// Requirements: M%BM==0, N%64==0, K%16==0, leading dims %4==0.
// ---------------------------------------------------------------------------
template<int BM, int THREADS>
__global__ __launch_bounds__(THREADS)
void tgemm_kernel(const float* __restrict__ A, const float* __restrict__ B,
                  const float* __restrict__ bias, float* __restrict__ C,
                  int K, int lda, int ldb, int ldc,
                  long long sAo, long long sAi,
                  long long sBo, long long sBi,
                  long long sCo, long long sCi,
                  int inner, float alpha, int transB)
{
    constexpr int WM_CNT = BM / 32;      // 4 or 2
    __shared__ uint32_t As[BM][20];      // [m][k], tf32 bits; stride 20 u32
    __shared__ uint32_t Bs[16][72];      // [k][pos(n)], tf32 bits

    int z = blockIdx.z;
    int o = z / inner, ii = z - o * inner;
    A += (long long)o * sAo + (long long)ii * sAi;
    B += (long long)o * sBo + (long long)ii * sBi;
    C += (long long)o * sCo + (long long)ii * sCi;

    const int tid  = threadIdx.x;
    const int lane = tid & 31;
    const int wid  = tid >> 5;
    const int g    = lane >> 2;     // groupID (0..7)
    const int tig  = lane & 3;      // threadID_in_group (0..3)
    const int wm   = wid % WM_CNT;  // warp M index
    const int wn   = wid / WM_CNT;  // warp N index (0..1)
    const int row0 = blockIdx.y * BM;
    const int col0 = blockIdx.x * 64;

    // A global load mapping
    const int am = tid >> 1;               // A row (0..BM-1)
    const int ak = (tid & 1) << 3;         // A k base (0 or 8)

    // B mappings
    const int bkNT  = (THREADS == 256) ? (tid >> 4) : (tid >> 4);       // non-trans k row
    const int bn4NT = (tid & 15) << 2;                                   // non-trans n base
    const int basNT = bpos(bn4NT);                                       // store base pos
    const int bnT   = tid & 63;                                          // transB n row
    const int bkT   = (THREADS == 256) ? ((tid >> 6) << 2)               // transB k base
                                       : ((tid >> 6) << 3);
    const int posT  = bpos(bnT);

    // ldmatrix per-lane base address for A
    uint32_t smemA = (uint32_t)__cvta_generic_to_shared(&As[0][0]);
    const uint32_t aldBase = smemA +
        (uint32_t)(((wm * 32 + (lane & 7) + ((lane >> 3) & 1) * 8) * 20 +
                    ((lane >> 4) << 2)) * 4);

    float4 pa0, pa1, pb0, pb1;
    {
        const float* pA = &A[(long long)(row0 + am) * lda + ak];
        pa0 = *(const float4*)pA;  pa1 = *(const float4*)(pA + 4);
    }
    if (!transB) {
        pb0 = *(const float4*)&B[(long long)bkNT * ldb + col0 + bn4NT];
        if (THREADS == 128)
            pb1 = *(const float4*)&B[(long long)(bkNT + 8) * ldb + col0 + bn4NT];
    } else {
        const float* pB = &B[(long long)(col0 + bnT) * ldb + bkT];
        pb0 = *(const float4*)pB;
        if (THREADS == 128) pb1 = *(const float4*)(pB + 4);
    }

    float acc[2][4][4];
    #pragma unroll
    for (int mt = 0; mt < 2; mt++)
        #pragma unroll
        for (int nt = 0; nt < 4; nt++)
            #pragma unroll
            for (int r = 0; r < 4; r++) acc[mt][nt][r] = 0.f;

    for (int kk = 0; kk < K; kk += 16) {
        __syncthreads();
        // ---- store prefetched tiles (convert to tf32 here) ----
        {
            uint4 u0 = make_uint4(f2tf32(pa0.x), f2tf32(pa0.y),
                                  f2tf32(pa0.z), f2tf32(pa0.w));
            uint4 u1 = make_uint4(f2tf32(pa1.x), f2tf32(pa1.y),
                                  f2tf32(pa1.z), f2tf32(pa1.w));
            *(uint4*)&As[am][ak]     = u0;
            *(uint4*)&As[am][ak + 4] = u1;
        }
        if (!transB) {
            // rows bkNT (and bkNT+8 for 128T), cols bn4NT..+3 -> pos base+4j
            Bs[bkNT][basNT +  0] = f2tf32(pb0.x);
            Bs[bkNT][basNT +  4] = f2tf32(pb0.y);
            Bs[bkNT][basNT +  8] = f2tf32(pb0.z);
            Bs[bkNT][basNT + 12] = f2tf32(pb0.w);
            if (THREADS == 128) {
                Bs[bkNT + 8][basNT +  0] = f2tf32(pb1.x);
                Bs[bkNT + 8][basNT +  4] = f2tf32(pb1.y);
                Bs[bkNT + 8][basNT +  8] = f2tf32(pb1.z);
                Bs[bkNT + 8][basNT + 12] = f2tf32(pb1.w);
            }
        } else {
            Bs[bkT + 0][posT] = f2tf32(pb0.x);
            Bs[bkT + 1][posT] = f2tf32(pb0.y);
            Bs[bkT + 2][posT] = f2tf32(pb0.z);
            Bs[bkT + 3][posT] = f2tf32(pb0.w);
            if (THREADS == 128) {
                Bs[bkT + 4][posT] = f2tf32(pb1.x);
                Bs[bkT + 5][posT] = f2tf32(pb1.y);
                Bs[bkT + 6][posT] = f2tf32(pb1.z);
                Bs[bkT + 7][posT] = f2tf32(pb1.w);
            }
        }
        __syncthreads();

        // ---- prefetch next K-tile ----
        if (kk + 16 < K) {
            const float* pA = &A[(long long)(row0 + am) * lda + kk + 16 + ak];
            pa0 = *(const float4*)pA;  pa1 = *(const float4*)(pA + 4);
            if (!transB) {
                pb0 = *(const float4*)&B[(long long)(kk + 16 + bkNT) * ldb + col0 + bn4NT];
                if (THREADS == 128)
                    pb1 = *(const float4*)&B[(long long)(kk + 16 + bkNT + 8) * ldb + col0 + bn4NT];
            } else {
                const float* pB = &B[(long long)(col0 + bnT) * ldb + kk + 16 + bkT];
                pb0 = *(const float4*)pB;
                if (THREADS == 128) pb1 = *(const float4*)(pB + 4);
            }
        }

        // ---- compute: two k8 steps ----
        #pragma unroll
        for (int k0 = 0; k0 < 16; k0 += 8) {
            uint32_t a[2][4];
            #pragma unroll
            for (int mt = 0; mt < 2; mt++) {
                LDSM_X4(a[mt][0], a[mt][1], a[mt][2], a[mt][3],
                        aldBase + (uint32_t)(mt * 1280 + k0 * 4));
            }
            // B fragments: one LDS.128 per k-half; component nt = n-tile nt
            uint4 q0 = *(const uint4*)&Bs[k0 + tig    ][wn * 32 + (g << 2)];
            uint4 q1 = *(const uint4*)&Bs[k0 + tig + 4][wn * 32 + (g << 2)];
            #pragma unroll
            for (int mt = 0; mt < 2; mt++) {
                MMA_TF32(acc[mt][0], a[mt], q0.x, q1.x);
                MMA_TF32(acc[mt][1], a[mt], q0.y, q1.y);
                MMA_TF32(acc[mt][2], a[mt], q0.z, q1.z);
                MMA_TF32(acc[mt][3], a[mt], q0.w, q1.w);
            }
        }
    }

    // Epilogue
    #pragma unroll
    for (int mt = 0; mt < 2; mt++) {
        int r0 = row0 + wm * 32 + mt * 16 + g;
        #pragma unroll
        for (int nt = 0; nt < 4; nt++) {
            int cc = col0 + wn * 32 + nt * 8 + (tig << 1);
            float b0 = 0.f, b1 = 0.f;
            if (bias) { b0 = bias[cc]; b1 = bias[cc + 1]; }
            float2 v0, v1;
            v0.x = fmaf(acc[mt][nt][0], alpha, b0);
            v0.y = fmaf(acc[mt][nt][1], alpha, b1);
            v1.x = fmaf(acc[mt][nt][2], alpha, b0);
            v1.y = fmaf(acc[mt][nt][3], alpha, b1);
            *(float2*)&C[(long long)r0 * ldc + cc]       = v0;
            *(float2*)&C[(long long)(r0 + 8) * ldc + cc] = v1;
        }
    }
}

// ---------------------------------------------------------------------------
// dec mean over H (float4):  decm[b,w,c] = mean_h kv[b, h*W + w, c]
// ---------------------------------------------------------------------------
__global__ void mean_h_kernel(const float* __restrict__ kv, float* __restrict__ out)
{
    int blk = blockIdx.x;              // 0 .. Bq*Ww/4-1
    int b  = blk / (Ww/4);
    int w4 = blk - b * (Ww/4);
    int wl = threadIdx.x / 96;         // 0..3
    int c4 = threadIdx.x % 96;         // float4 index
    int w = w4 * 4 + wl;
    float4 s = make_float4(0.f,0.f,0.f,0.f);
    #pragma unroll
    for (int h = 0; h < Hh; h++) {
        const float4 v = *(const float4*)&kv[((long long)(b*Nkv + h*Ww + w)) * Cq + c4*4];
        s.x += v.x; s.y += v.y; s.z += v.z; s.w += v.w;
    }
    const float inv = 1.0f / Hh;
    s.x *= inv; s.y *= inv; s.z *= inv; s.w *= inv;
    *(float4*)&out[((long long)(b*Ww + w)) * Cq + c4*4] = s;
}

// ---------------------------------------------------------------------------
// LayerNorm over C=384 (128 threads, 3 elems/thread)
// ---------------------------------------------------------------------------
__global__ void ln_kernel(const float* __restrict__ x, const float* __restrict__ g,
                          const float* __restrict__ b, float* __restrict__ y)
{
    long long row = blockIdx.x;
    const float* px = x + row * Cq;
    float* py = y + row * Cq;
    float v[3]; float s = 0.f;
    #pragma unroll
    for (int j = 0; j < 3; j++) { v[j] = px[threadIdx.x + j*128]; s += v[j]; }
    float mean = blk_reduce_sum(s) * (1.0f / Cq);
    float sq = 0.f;
    #pragma unroll
    for (int j = 0; j < 3; j++) { float d = v[j] - mean; sq += d*d; }
    float var = blk_reduce_sum(sq) * (1.0f / Cq);
    float rstd = rsqrtf(var + 1e-6f);
    #pragma unroll
    for (int j = 0; j < 3; j++) {
        int c = threadIdx.x + j*128;
        py[c] = (v[j] - mean) * rstd * g[c] + b[c];
    }
}

// ---------------------------------------------------------------------------
// Row softmax (in place), row length L
// ---------------------------------------------------------------------------
__global__ void softmax_kernel(float* __restrict__ x, int L)
{
    long long row = blockIdx.x;
    float* p = x + row * (long long)L;
    float m = -3.4e38f;
    for (int i = threadIdx.x; i < L; i += blockDim.x) m = fmaxf(m, p[i]);
    m = blk_reduce_max(m);
    float s = 0.f;
    for (int i = threadIdx.x; i < L; i += blockDim.x) {
        float e = expf(p[i] - m); p[i] = e; s += e;
    }
    s = blk_reduce_sum(s);
    float inv = 1.0f / s;
    for (int i = threadIdx.x; i < L; i += blockDim.x) p[i] *= inv;
}

// ---------------------------------------------------------------------------
// Fused gaussian-window + softmax over W=512 (in place). 256 threads.
// ---------------------------------------------------------------------------
__global__ void gauss_softmax_kernel(float* __restrict__ x, const float* __restrict__ pt)
{
    long long row = blockIdx.x;
    float* p = x + row * (long long)Ww;
    const float c = pt[row];
    float v[2];
    #pragma unroll
    for (int j = 0; j < 2; j++) {
        int i = threadIdx.x + j*256;
        float d = (float)i - c;
        v[j] = p[i] * expf(-d*d * (1.0f/18.0f));
    }
    float m = fmaxf(v[0], v[1]);
    m = blk_reduce_max(m);
    float s = 0.f;
    #pragma unroll
    for (int j = 0; j < 2; j++) { v[j] = expf(v[j] - m); s += v[j]; }
    s = blk_reduce_sum(s);
    float inv = 1.0f / s;
    #pragma unroll
    for (int j = 0; j < 2; j++) p[threadIdx.x + j*256] = v[j] * inv;
}

// ---------------------------------------------------------------------------
// p_t[row] = sigmoid( sum_c tanh(tbuf[row,c]) * vp_w[c] + vp_b ) * W
// ---------------------------------------------------------------------------
__global__ void pt_kernel(const float* __restrict__ t, const float* __restrict__ vw,
                          const float* __restrict__ vb, float* __restrict__ pt)
{
    long long row = blockIdx.x;
    float s = 0.f;
    for (int c = threadIdx.x; c < Cq; c += blockDim.x)
        s += tanhf(t[row*Cq + c]) * vw[c];
    s = blk_reduce_sum(s);
    if (threadIdx.x == 0)
        pt[row] = (float)Ww / (1.0f + expf(-(s + vb[0])));
}

// ---------------------------------------------------------------------------
// Host launcher
// ---------------------------------------------------------------------------
static void gemm(const float* A, const float* B, const float* bias, float* C,
                 int M, int N, int K, int lda, int ldb, int ldc,
                 long long sAo, long long sAi, long long sBo, long long sBi,
                 long long sCo, long long sCi, int outer, int inner,
                 float alpha, int transB)
{
    int batches = outer * inner;
    if (M % 128 == 0 && M > 128) {
        dim3 grid(N / 64, M / 128, batches);
        tgemm_kernel<128, 256><<<grid, 256>>>(A, B, bias, C, K, lda, ldb, ldc,
                                              sAo, sAi, sBo, sBi, sCo, sCi,
                                              inner, alpha, transB);
    } else {
        dim3 grid(N / 64, M / 64, batches);
        tgemm_kernel<64, 128><<<grid, 128>>>(A, B, bias, C, K, lda, ldb, ldc,
                                             sAo, sAi, sBo, sBi, sCo, sCi,
                                             inner, alpha, transB);
    }
}

extern "C" void kernel_launch(void* const* d_in, const int* in_sizes, int n_in,
                              void* d_out, int out_size)
{
    const float* q         = (const float*)d_in[0];
    const float* kv        = (const float*)d_in[1];
    const float* Wq        = (const float*)d_in[2];
    const float* Wkv       = (const float*)d_in[3];
    const float* Wproj     = (const float*)d_in[4];
    const float* bproj     = (const float*)d_in[5];
    const float* Wp_w      = (const float*)d_in[6];
    const float* Wp_b      = (const float*)d_in[7];
    const float* vp_w      = (const float*)d_in[8];
    const float* vp_b      = (const float*)d_in[9];
    const float* Wqpos     = (const float*)d_in[10];
    const float* bqpos     = (const float*)d_in[11];
    const float* Wrctc     = (const float*)d_in[12];
    const float* brctc     = (const float*)d_in[13];
    const float* ca1_Wq    = (const float*)d_in[14];
    const float* ca1_Wkv   = (const float*)d_in[15];
    const float* ca1_Wproj = (const float*)d_in[16];
    const float* ca1_bproj = (const float*)d_in[17];
    const float* ca2_Wq    = (const float*)d_in[18];
    const float* ca2_Wkv   = (const float*)d_in[19];
    const float* ca2_Wproj = (const float*)d_in[20];
    const float* ca2_bproj = (const float*)d_in[21];
    const float* g_q1      = (const float*)d_in[22];
    const float* b_q1      = (const float*)d_in[23];
    const float* g_kv1     = (const float*)d_in[24];
    const float* b_kv1     = (const float*)d_in[25];
    const float* g_q2      = (const float*)d_in[26];
    const float* b_q2      = (const float*)d_in[27];
    const float* g_kv2     = (const float*)d_in[28];
    const float* b_kv2     = (const float*)d_in[29];
    float* out = (float*)d_out;

    float* scr = nullptr;
    cudaGetSymbolAddress((void**)&scr, SCR);

    float* decm   = scr + OFF_DECM;
    float* dec    = scr + OFF_DEC;
    float* lndec  = scr + OFF_LNDEC;
    float* kvmain = scr + OFF_KVMAIN;
    float* kv2    = scr + OFF_KV2;
    float* kv1    = scr + OFF_KV1;
    float* qh     = scr + OFF_QH;
    float* p0     = scr + OFF_P0;
    float* lnA    = scr + OFF_LNA;
    float* lnB    = scr + OFF_LNB;
    float* qh1    = scr + OFF_QH1;
    float* x1     = scr + OFF_X1;
    float* p1     = scr + OFF_P1;
    float* qh2    = scr + OFF_QH2;
    float* x2     = scr + OFF_X2;
    float* p2     = scr + OFF_P2;
    float* tbuf   = scr + OFF_TBUF;
    float* xmain  = scr + OFF_XMAIN;
    float* sc1    = scr + OFF_SC1;
    float* sc2    = scr + OFF_SC2;
    float* scm    = scr + OFF_SCM;
    float* pt     = scr + OFF_PT;

    const float scale_main = rsqrtf((float)Cq);   // hd = 384 for nh=1
    const float scale_h    = rsqrtf((float)HD2);  // hd = 192 for nh=2

    // 1. dec mean over H
    mean_h_kernel<<<Bq*Ww/4, 384>>>(kv, decm);

    // 2. dec = decm @ Wrctc + brctc      [B, 512, 384]
    gemm(decm, Wrctc, brctc, dec, Ww, Cq, Cq, Cq, Cq, Cq,
         (long long)Ww*Cq, 0, 0, 0, (long long)Ww*Cq, 0, Bq, 1, 1.0f, 0);

    // 3. qh = (q @ Wq) * scale_main     [B, 128, 384]
    gemm(q, Wq, nullptr, qh, Sq, Cq, Cq, Cq, Cq, Cq,
         (long long)Sq*Cq, 0, 0, 0, (long long)Sq*Cq, 0, Bq, 1, scale_main, 0);

    // 4. kvmain = dec @ Wkv             [B, 512, 768]
    gemm(dec, Wkv, nullptr, kvmain, Ww, 2*Cq, Cq, Cq, 2*Cq, 2*Cq,
         (long long)Ww*Cq, 0, 0, 0, (long long)Ww*2*Cq, 0, Bq, 1, 1.0f, 0);

    // 5. p0 = q @ Wqpos + bqpos
    gemm(q, Wqpos, bqpos, p0, Sq, Cq, Cq, Cq, Cq, Cq,
         (long long)Sq*Cq, 0, 0, 0, (long long)Sq*Cq, 0, Bq, 1, 1.0f, 0);

    // 6/7. LayerNorms for ca1
    ln_kernel<<<Bq*Sq, 128>>>(p0, g_q1, b_q1, lnA);
    ln_kernel<<<Bq*Sq, 128>>>(q,  g_kv1, b_kv1, lnB);

    // 8. qh1 = (lnA @ ca1_Wq) * scale_h
    gemm(lnA, ca1_Wq, nullptr, qh1, Sq, Cq, Cq, Cq, Cq, Cq,
         (long long)Sq*Cq, 0, 0, 0, (long long)Sq*Cq, 0, Bq, 1, scale_h, 0);

    // 9. kv1 = lnB @ ca1_Wkv            [B, 128, 768]
    gemm(lnB, ca1_Wkv, nullptr, kv1, Sq, 2*Cq, Cq, Cq, 2*Cq, 2*Cq,
         (long long)Sq*Cq, 0, 0, 0, (long long)Sq*2*Cq, 0, Bq, 1, 1.0f, 0);

    // 10. sc1[b,h] = qh1_h @ k1_h^T     [B, 2, 128, 128]
    gemm(qh1, kv1, nullptr, sc1, Sq, Sq, HD2, Cq, 2*Cq, Sq,
         (long long)Sq*Cq, HD2, (long long)Sq*2*Cq, HD2,
         (long long)2*Sq*Sq, (long long)Sq*Sq, Bq, 2, 1.0f, 1);

    // 11. softmax over 128 keys
    softmax_kernel<<<Bq*2*Sq, 128>>>(sc1, Sq);

    // 12. x1[b,:,h*192:] = sc1 @ v1_h   [B, 128, 384]
    gemm(sc1, kv1 + Cq, nullptr, x1, Sq, HD2, Sq, Sq, 2*Cq, Cq,
         (long long)2*Sq*Sq, (long long)Sq*Sq, (long long)Sq*2*Cq, HD2,
         (long long)Sq*Cq, HD2, Bq, 2, 1.0f, 0);

    // 13. p1 = x1 @ ca1_Wproj + ca1_bproj
    gemm(x1, ca1_Wproj, ca1_bproj, p1, Sq, Cq, Cq, Cq, Cq, Cq,
         (long long)Sq*Cq, 0, 0, 0, (long long)Sq*Cq, 0, Bq, 1, 1.0f, 0);

    // 14/15. LayerNorms for ca2
    ln_kernel<<<Bq*Sq, 128>>>(p1, g_q2, b_q2, lnA);   // reuse lnA
    ln_kernel<<<Bq*Ww, 128>>>(dec, g_kv2, b_kv2, lndec);

    // 16. qh2 = (lnA @ ca2_Wq) * scale_h
    gemm(lnA, ca2_Wq, nullptr, qh2, Sq, Cq, Cq, Cq, Cq, Cq,
         (long long)Sq*Cq, 0, 0, 0, (long long)Sq*Cq, 0, Bq, 1, scale_h, 0);

    // 17. kv2 = lndec @ ca2_Wkv         [B, 512, 768]
    gemm(lndec, ca2_Wkv, nullptr, kv2, Ww, 2*Cq, Cq, Cq, 2*Cq, 2*Cq,
         (long long)Ww*Cq, 0, 0, 0, (long long)Ww*2*Cq, 0, Bq, 1, 1.0f, 0);

    // 18. sc2[b,h] = qh2_h @ k2_h^T     [B, 2, 128, 512]
    gemm(qh2, kv2, nullptr, sc2, Sq, Ww, HD2, Cq, 2*Cq, Ww,
         (long long)Sq*Cq, HD2, (long long)Ww*2*Cq, HD2,
         (long long)2*Sq*Ww, (long long)Sq*Ww, Bq, 2, 1.0f, 1);

    // 19. softmax over 512 keys
    softmax_kernel<<<Bq*2*Sq, 256>>>(sc2, Ww);

    // 20. x2 = sc2 @ v2_h               [B, 128, 384]
    gemm(sc2, kv2 + Cq, nullptr, x2, Sq, HD2, Ww, Ww, 2*Cq, Cq,
         (long long)2*Sq*Ww, (long long)Sq*Ww, (long long)Ww*2*Cq, HD2,
         (long long)Sq*Cq, HD2, Bq, 2, 1.0f, 0);

    // 21. p2 = x2 @ ca2_Wproj + ca2_bproj
    gemm(x2, ca2_Wproj, ca2_bproj, p2, Sq, Cq, Cq, Cq, Cq, Cq,
         (long long)Sq*Cq, 0, 0, 0, (long long)Sq*Cq, 0, Bq, 1, 1.0f, 0);

    // 22. tbuf = p2 @ Wp_w + Wp_b
    gemm(p2, Wp_w, Wp_b, tbuf, Sq, Cq, Cq, Cq, Cq, Cq,
         (long long)Sq*Cq, 0, 0, 0, (long long)Sq*Cq, 0, Bq, 1, 1.0f, 0);

    // 23. p_t
    pt_kernel<<<Bq*Sq, 128>>>(tbuf, vp_w, vp_b, pt);

    // 24. main scores = qh @ k_main^T   [B, 128, 512]
    gemm(qh, kvmain, nullptr, scm, Sq, Ww, Cq, Cq, 2*Cq, Ww,
         (long long)Sq*Cq, 0, (long long)Ww*2*Cq, 0,
         (long long)Sq*Ww, 0, Bq, 1, 1.0f, 1);

    // 25/26. fused gaussian window + softmax over W
    gauss_softmax_kernel<<<Bq*Sq, 256>>>(scm, pt);

    // 27. xmain = scm @ v_main          [B, 128, 384]
    gemm(scm, kvmain + Cq, nullptr, xmain, Sq, Cq, Ww, Ww, 2*Cq, Cq,
         (long long)Sq*Ww, 0, (long long)Ww*2*Cq, 0,
         (long long)Sq*Cq, 0, Bq, 1, 1.0f, 0);

    // 28. out = xmain @ Wproj + bproj
    gemm(xmain, Wproj, bproj, out, Sq, Cq, Cq, Cq, Cq, Cq,
         (long long)Sq*Cq, 0, 0, 0, (long long)Sq*Cq, 0, Bq, 1, 1.0f, 0);
}

// round 16
// speedup vs baseline: 1.0225x; 1.0225x over previous
#include <cuda_runtime.h>
#include <cuda_bf16.h>
#include <math.h>
#include <stdint.h>

// Problem constants (fixed by setup_inputs)
#define Bq   32
#define Sq   128
#define Cq   384
#define Hh   8
#define Ww   512
#define Nkv  (Hh*Ww)        // 4096
#define HD2  192            // head dim for nh=2 cross-attn
// SIGMA = 3 -> 2*sigma^2 = 18

// ---------------------------------------------------------------------------
// Scratch (single __device__ global; no allocations allowed)
// ---------------------------------------------------------------------------
#define SZ_BWC   (Bq*Ww*Cq)
#define SZ_BW2C  (Bq*Ww*2*Cq)
#define SZ_BSC   (Bq*Sq*Cq)
#define SZ_BS2C  (Bq*Sq*2*Cq)
#define SZ_SC1   (Bq*2*Sq*Sq)
#define SZ_SC2   (Bq*2*Sq*Ww)
#define SZ_SCM   (Bq*Sq*Ww)
#define SZ_PT    (Bq*Sq)

#define OFF_DECM   0
#define OFF_DEC    (OFF_DECM + SZ_BWC)
#define OFF_LNDEC  (OFF_DEC + SZ_BWC)
#define OFF_KVMAIN (OFF_LNDEC + SZ_BWC)
#define OFF_KV2    (OFF_KVMAIN + SZ_BW2C)
#define OFF_KV1    (OFF_KV2 + SZ_BW2C)
#define OFF_QH     (OFF_KV1 + SZ_BS2C)
#define OFF_P0     (OFF_QH   + SZ_BSC)
#define OFF_LNA    (OFF_P0   + SZ_BSC)
#define OFF_LNB    (OFF_LNA  + SZ_BSC)
#define OFF_QH1    (OFF_LNB  + SZ_BSC)
#define OFF_X1     (OFF_QH1  + SZ_BSC)
#define OFF_P1     (OFF_X1   + SZ_BSC)
#define OFF_QH2    (OFF_P1   + SZ_BSC)
#define OFF_X2     (OFF_QH2  + SZ_BSC)
#define OFF_P2     (OFF_X2   + SZ_BSC)
#define OFF_TBUF   (OFF_P2   + SZ_BSC)
#define OFF_XMAIN  (OFF_TBUF + SZ_BSC)
#define OFF_SC1    (OFF_XMAIN+ SZ_BSC)
#define OFF_SC2    (OFF_SC1  + SZ_SC1)
#define OFF_SCM    (OFF_SC2  + SZ_SC2)
#define OFF_PT     (OFF_SCM  + SZ_SCM)
#define SCR_TOTAL  (OFF_PT + SZ_PT)

__device__ float SCR[SCR_TOTAL];

// ---------------------------------------------------------------------------
// Block reductions
// ---------------------------------------------------------------------------
__device__ __forceinline__ float blk_reduce_sum(float v) {
    __shared__ float sh[32];
    int lane = threadIdx.x & 31, w = threadIdx.x >> 5;
    #pragma unroll
    for (int o = 16; o; o >>= 1) v += __shfl_xor_sync(0xffffffffu, v, o);
    __syncthreads();
    if (lane == 0) sh[w] = v;
    __syncthreads();
    int nw = (blockDim.x + 31) >> 5;
    float r = (lane < nw) ? sh[lane] : 0.f;
    #pragma unroll
    for (int o = 16; o; o >>= 1) r += __shfl_xor_sync(0xffffffffu, r, o);
    return r;
}

__device__ __forceinline__ float blk_reduce_max(float v) {
    __shared__ float sh[32];
    int lane = threadIdx.x & 31, w = threadIdx.x >> 5;
    #pragma unroll
    for (int o = 16; o; o >>= 1) v = fmaxf(v, __shfl_xor_sync(0xffffffffu, v, o));
    __syncthreads();
    if (lane == 0) sh[w] = v;
    __syncthreads();
    int nw = (blockDim.x + 31) >> 5;
    float r = (lane < nw) ? sh[lane] : -3.4e38f;
    #pragma unroll
    for (int o = 16; o; o >>= 1) r = fmaxf(r, __shfl_xor_sync(0xffffffffu, r, o));
    return r;
}

// ---------------------------------------------------------------------------
// tf32 helpers
// ---------------------------------------------------------------------------
__device__ __forceinline__ uint32_t f2tf32(float f) {
    uint32_t u;
    asm("cvt.rna.tf32.f32 %0, %1;" : "=r"(u) : "f"(f));
    return u;
}

#define MMA_TF32(c, a, b0_, b1_)                                              \
    asm("mma.sync.aligned.m16n8k8.row.col.f32.tf32.tf32.f32 "                 \
        "{%0,%1,%2,%3}, {%4,%5,%6,%7}, {%8,%9}, {%0,%1,%2,%3};"               \
        : "+f"((c)[0]), "+f"((c)[1]), "+f"((c)[2]), "+f"((c)[3])              \
        : "r"((a)[0]), "r"((a)[1]), "r"((a)[2]), "r"((a)[3]),                 \
          "r"(b0_), "r"(b1_))

#define LDSM_X4(r0, r1, r2, r3, addr)                                         \
    asm volatile("ldmatrix.sync.aligned.m8n8.x4.shared.b16 {%0,%1,%2,%3}, [%4];" \
        : "=r"(r0), "=r"(r1), "=r"(r2), "=r"(r3) : "r"(addr))

// ---------------------------------------------------------------------------
// TF32 tensor-core GEMM: C = alpha * A @ op(B) (+ bias)
// Block BM x BN, THREADS = 2*BM, warp tile 32 x (BN/2),
// mma m16n8k8 (2 M-tiles x BN/16 N-tiles per warp), K-tile 16,
// register-prefetch double buffering.
// A smem: row-major [m][16k], stride 20 u32; A fragments via ldmatrix.x4
//   (row starts 20r mod 32 = perfect bank permutation -> conflict-free).
// B smem: [k][n], stride BN+8 (== 8 mod 32) -> scalar fragment loads
//   (lane bank = 8*tig + g (+8*nt)) conflict-free (proven R9).
// BN=128 path: transB must be 0 (enforced by launcher).
// Requirements: M%BM==0, N%BN==0, K%16==0, leading dims %4==0.
// ---------------------------------------------------------------------------
template<int BM, int BN, int THREADS>
__global__ __launch_bounds__(THREADS)
void tgemm_kernel(const float* __restrict__ A, const float* __restrict__ B,
                  const float* __restrict__ bias, float* __restrict__ C,
                  int K, int lda, int ldb, int ldc,
                  long long sAo, long long sAi,
                  long long sBo, long long sBi,
                  long long sCo, long long sCi,
                  int inner, float alpha, int transB)
{
    constexpr int WM_CNT = BM / 32;      // 4 or 2
    constexpr int WNT    = BN / 16;      // N-tiles per warp (4 or 8)
    constexpr int BST    = BN + 8;       // 72 or 136; both == 8 (mod 32)
    __shared__ uint32_t As[BM][20];      // [m][k], tf32 bits; stride 20 u32
    __shared__ uint32_t Bs[16][BST];     // [k][n], tf32 bits

    int z = blockIdx.z;
    int o = z / inner, ii = z - o * inner;
    A += (long long)o * sAo + (long long)ii * sAi;
    B += (long long)o * sBo + (long long)ii * sBi;
    C += (long long)o * sCo + (long long)ii * sCi;

    const int tid  = threadIdx.x;
    const int lane = tid & 31;
    const int wid  = tid >> 5;
    const int g    = lane >> 2;     // groupID (0..7)
    const int tig  = lane & 3;      // threadID_in_group (0..3)
    const int wm   = wid % WM_CNT;  // warp M index
    const int wn   = wid / WM_CNT;  // warp N index (0..1)
    const int row0 = blockIdx.y * BM;
    const int col0 = blockIdx.x * BN;

    // Global load mappings
    const int am = tid >> 1;               // A row (0..BM-1)
    const int ak = (tid & 1) << 3;         // A k base (0 or 8)

    // ldmatrix per-lane base address for A
    uint32_t smemA = (uint32_t)__cvta_generic_to_shared(&As[0][0]);
    const uint32_t aldBase = smemA +
        (uint32_t)(((wm * 32 + (lane & 7) + ((lane >> 3) & 1) * 8) * 20 +
                    ((lane >> 4) << 2)) * 4);

    float4 pa0, pa1, pb0, pb1;
    {
        const float* pA = &A[(long long)(row0 + am) * lda + ak];
        pa0 = *(const float4*)pA;  pa1 = *(const float4*)(pA + 4);
    }
    if (BN == 128) {
        // non-trans only: bk = tid>>4, bn8 = (tid&15)*8
        int bk = tid >> 4, bn8 = (tid & 15) << 3;
        const float* pB = &B[(long long)bk * ldb + col0 + bn8];
        pb0 = *(const float4*)pB;  pb1 = *(const float4*)(pB + 4);
    } else if (!transB) {
        if (THREADS == 256) {
            int bk = tid >> 4, bn4 = (tid & 15) << 2;
            pb0 = *(const float4*)&B[(long long)bk * ldb + col0 + bn4];
        } else {
            int bk = tid >> 3, bn8 = (tid & 7) << 3;
            const float* pB = &B[(long long)bk * ldb + col0 + bn8];
            pb0 = *(const float4*)pB;  pb1 = *(const float4*)(pB + 4);
        }
    } else {
        if (THREADS == 256) {
            int bn = tid >> 2, bk4 = (tid & 3) << 2;
            pb0 = *(const float4*)&B[(long long)(col0 + bn) * ldb + bk4];
        } else {
            int bn = tid >> 1, bk8 = (tid & 1) << 3;
            const float* pB = &B[(long long)(col0 + bn) * ldb + bk8];
            pb0 = *(const float4*)pB;  pb1 = *(const float4*)(pB + 4);
        }
    }

    float acc[2][WNT][4];
    #pragma unroll
    for (int mt = 0; mt < 2; mt++)
        #pragma unroll
        for (int nt = 0; nt < WNT; nt++)
            #pragma unroll
            for (int r = 0; r < 4; r++) acc[mt][nt][r] = 0.f;

    for (int kk = 0; kk < K; kk += 16) {
        __syncthreads();
        // ---- store prefetched tiles (convert to tf32 once here) ----
        {
            uint4 u0 = make_uint4(f2tf32(pa0.x), f2tf32(pa0.y),
                                  f2tf32(pa0.z), f2tf32(pa0.w));
            uint4 u1 = make_uint4(f2tf32(pa1.x), f2tf32(pa1.y),
                                  f2tf32(pa1.z), f2tf32(pa1.w));
            *(uint4*)&As[am][ak]     = u0;
            *(uint4*)&As[am][ak + 4] = u1;
        }
        if (BN == 128) {
            int bk = tid >> 4, bn8 = (tid & 15) << 3;
            uint4 u0 = make_uint4(f2tf32(pb0.x), f2tf32(pb0.y),
                                  f2tf32(pb0.z), f2tf32(pb0.w));
            uint4 u1 = make_uint4(f2tf32(pb1.x), f2tf32(pb1.y),
                                  f2tf32(pb1.z), f2tf32(pb1.w));
            *(uint4*)&Bs[bk][bn8]     = u0;
            *(uint4*)&Bs[bk][bn8 + 4] = u1;
        } else if (!transB) {
            if (THREADS == 256) {
                int bk = tid >> 4, bn4 = (tid & 15) << 2;
                uint4 u = make_uint4(f2tf32(pb0.x), f2tf32(pb0.y),
                                     f2tf32(pb0.z), f2tf32(pb0.w));
                *(uint4*)&Bs[bk][bn4] = u;
            } else {
                int bk = tid >> 3, bn8 = (tid & 7) << 3;
                uint4 u0 = make_uint4(f2tf32(pb0.x), f2tf32(pb0.y),
                                      f2tf32(pb0.z), f2tf32(pb0.w));
                uint4 u1 = make_uint4(f2tf32(pb1.x), f2tf32(pb1.y),
                                      f2tf32(pb1.z), f2tf32(pb1.w));
                *(uint4*)&Bs[bk][bn8]     = u0;
                *(uint4*)&Bs[bk][bn8 + 4] = u1;
            }
        } else {
            if (THREADS == 256) {
                int bn = tid >> 2, bk4 = (tid & 3) << 2;
                Bs[bk4+0][bn] = f2tf32(pb0.x); Bs[bk4+1][bn] = f2tf32(pb0.y);
                Bs[bk4+2][bn] = f2tf32(pb0.z); Bs[bk4+3][bn] = f2tf32(pb0.w);
            } else {
                int bn = tid >> 1, bk8 = (tid & 1) << 3;
                Bs[bk8+0][bn] = f2tf32(pb0.x); Bs[bk8+1][bn] = f2tf32(pb0.y);
                Bs[bk8+2][bn] = f2tf32(pb0.z); Bs[bk8+3][bn] = f2tf32(pb0.w);
                Bs[bk8+4][bn] = f2tf32(pb1.x); Bs[bk8+5][bn] = f2tf32(pb1.y);
                Bs[bk8+6][bn] = f2tf32(pb1.z); Bs[bk8+7][bn] = f2tf32(pb1.w);
            }
        }
        __syncthreads();

        // ---- prefetch next K-tile ----
        if (kk + 16 < K) {
            const float* pA = &A[(long long)(row0 + am) * lda + kk + 16 + ak];
            pa0 = *(const float4*)pA;  pa1 = *(const float4*)(pA + 4);
            if (BN == 128) {
                int bk = tid >> 4, bn8 = (tid & 15) << 3;
                const float* pB = &B[(long long)(kk + 16 + bk) * ldb + col0 + bn8];
                pb0 = *(const float4*)pB;  pb1 = *(const float4*)(pB + 4);
            } else if (!transB) {
                if (THREADS == 256) {
                    int bk = tid >> 4, bn4 = (tid & 15) << 2;
                    pb0 = *(const float4*)&B[(long long)(kk + 16 + bk) * ldb + col0 + bn4];
                } else {
                    int bk = tid >> 3, bn8 = (tid & 7) << 3;
                    const float* pB = &B[(long long)(kk + 16 + bk) * ldb + col0 + bn8];
                    pb0 = *(const float4*)pB;  pb1 = *(const float4*)(pB + 4);
                }
            } else {
                if (THREADS == 256) {
                    int bn = tid >> 2, bk4 = (tid & 3) << 2;
                    pb0 = *(const float4*)&B[(long long)(col0 + bn) * ldb + kk + 16 + bk4];
                } else {
                    int bn = tid >> 1, bk8 = (tid & 1) << 3;
                    const float* pB = &B[(long long)(col0 + bn) * ldb + kk + 16 + bk8];
                    pb0 = *(const float4*)pB;  pb1 = *(const float4*)(pB + 4);
                }
            }
        }

        // ---- compute: two k8 steps ----
        #pragma unroll
        for (int k0 = 0; k0 < 16; k0 += 8) {
            uint32_t a[2][4];
            #pragma unroll
            for (int mt = 0; mt < 2; mt++) {
                LDSM_X4(a[mt][0], a[mt][1], a[mt][2], a[mt][3],
                        aldBase + (uint32_t)(mt * 1280 + k0 * 4));
            }
            #pragma unroll
            for (int nt = 0; nt < WNT; nt++) {
                int nbase = wn * (BN/2) + nt * 8 + g;
                uint32_t b0 = Bs[k0 + tig    ][nbase];
                uint32_t b1 = Bs[k0 + tig + 4][nbase];
                MMA_TF32(acc[0][nt], a[0], b0, b1);
                MMA_TF32(acc[1][nt], a[1], b0, b1);
            }
        }
    }

    // Epilogue
    #pragma unroll
    for (int mt = 0; mt < 2; mt++) {
        int r0 = row0 + wm * 32 + mt * 16 + g;
        #pragma unroll
        for (int nt = 0; nt < WNT; nt++) {
            int cc = col0 + wn * (BN/2) + nt * 8 + (tig << 1);
            float b0 = 0.f, b1 = 0.f;
            if (bias) { b0 = bias[cc]; b1 = bias[cc + 1]; }
            float2 v0, v1;
            v0.x = fmaf(acc[mt][nt][0], alpha, b0);
            v0.y = fmaf(acc[mt][nt][1], alpha, b1);
            v1.x = fmaf(acc[mt][nt][2], alpha, b0);
            v1.y = fmaf(acc[mt][nt][3], alpha, b1);
            *(float2*)&C[(long long)r0 * ldc + cc]       = v0;
            *(float2*)&C[(long long)(r0 + 8) * ldc + cc] = v1;
        }
    }
}

// ---------------------------------------------------------------------------
// dec mean over H (float4):  decm[b,w,c] = mean_h kv[b, h*W + w, c]
// ---------------------------------------------------------------------------
__global__ void mean_h_kernel(const float* __restrict__ kv, float* __restrict__ out)
{
    int blk = blockIdx.x;              // 0 .. Bq*Ww/4-1
    int b  = blk / (Ww/4);
    int w4 = blk - b * (Ww/4);
    int wl = threadIdx.x / 96;         // 0..3
    int c4 = threadIdx.x % 96;         // float4 index
    int w = w4 * 4 + wl;
    float4 s = make_float4(0.f,0.f,0.f,0.f);
    #pragma unroll
    for (int h = 0; h < Hh; h++) {
        const float4 v = *(const float4*)&kv[((long long)(b*Nkv + h*Ww + w)) * Cq + c4*4];
        s.x += v.x; s.y += v.y; s.z += v.z; s.w += v.w;
    }
    const float inv = 1.0f / Hh;
    s.x *= inv; s.y *= inv; s.z *= inv; s.w *= inv;
    *(float4*)&out[((long long)(b*Ww + w)) * Cq + c4*4] = s;
}

// ---------------------------------------------------------------------------
// LayerNorm over C=384 (128 threads, 3 elems/thread)
// ---------------------------------------------------------------------------
__global__ void ln_kernel(const float* __restrict__ x, const float* __restrict__ g,
                          const float* __restrict__ b, float* __restrict__ y)
{
    long long row = blockIdx.x;
    const float* px = x + row * Cq;
    float* py = y + row * Cq;
    float v[3]; float s = 0.f;
    #pragma unroll
    for (int j = 0; j < 3; j++) { v[j] = px[threadIdx.x + j*128]; s += v[j]; }
    float mean = blk_reduce_sum(s) * (1.0f / Cq);
    float sq = 0.f;
    #pragma unroll
    for (int j = 0; j < 3; j++) { float d = v[j] - mean; sq += d*d; }
    float var = blk_reduce_sum(sq) * (1.0f / Cq);
    float rstd = rsqrtf(var + 1e-6f);
    #pragma unroll
    for (int j = 0; j < 3; j++) {
        int c = threadIdx.x + j*128;
        py[c] = (v[j] - mean) * rstd * g[c] + b[c];
    }
}

// ---------------------------------------------------------------------------
// Row softmax (in place), row length L
// ---------------------------------------------------------------------------
__global__ void softmax_kernel(float* __restrict__ x, int L)
{
    long long row = blockIdx.x;
    float* p = x + row * (long long)L;
    float m = -3.4e38f;
    for (int i = threadIdx.x; i < L; i += blockDim.x) m = fmaxf(m, p[i]);
    m = blk_reduce_max(m);
    float s = 0.f;
    for (int i = threadIdx.x; i < L; i += blockDim.x) {
        float e = expf(p[i] - m); p[i] = e; s += e;
    }
    s = blk_reduce_sum(s);
    float inv = 1.0f / s;
    for (int i = threadIdx.x; i < L; i += blockDim.x) p[i] *= inv;
}

// ---------------------------------------------------------------------------
// Fused gaussian-window + softmax over W=512 (in place). 256 threads.
// ---------------------------------------------------------------------------
__global__ void gauss_softmax_kernel(float* __restrict__ x, const float* __restrict__ pt)
{
    long long row = blockIdx.x;
    float* p = x + row * (long long)Ww;
    const float c = pt[row];
    float v[2];
    #pragma unroll
    for (int j = 0; j < 2; j++) {
        int i = threadIdx.x + j*256;
        float d = (float)i - c;
        v[j] = p[i] * expf(-d*d * (1.0f/18.0f));
    }
    float m = fmaxf(v[0], v[1]);
    m = blk_reduce_max(m);
    float s = 0.f;
    #pragma unroll
    for (int j = 0; j < 2; j++) { v[j] = expf(v[j] - m); s += v[j]; }
    s = blk_reduce_sum(s);
    float inv = 1.0f / s;
    #pragma unroll
    for (int j = 0; j < 2; j++) p[threadIdx.x + j*256] = v[j] * inv;
}

// ---------------------------------------------------------------------------
// p_t[row] = sigmoid( sum_c tanh(tbuf[row,c]) * vp_w[c] + vp_b ) * W
// ---------------------------------------------------------------------------
__global__ void pt_kernel(const float* __restrict__ t, const float* __restrict__ vw,
                          const float* __restrict__ vb, float* __restrict__ pt)
{
    long long row = blockIdx.x;
    float s = 0.f;
    for (int c = threadIdx.x; c < Cq; c += blockDim.x)
        s += tanhf(t[row*Cq + c]) * vw[c];
    s = blk_reduce_sum(s);
    if (threadIdx.x == 0)
        pt[row] = (float)Ww / (1.0f + expf(-(s + vb[0])));
}

// ---------------------------------------------------------------------------
// Host launcher
// ---------------------------------------------------------------------------
static void gemm(const float* A, const float* B, const float* bias, float* C,
                 int M, int N, int K, int lda, int ldb, int ldc,
                 long long sAo, long long sAi, long long sBo, long long sBi,
                 long long sCo, long long sCi, int outer, int inner,
                 float alpha, int transB)
{
    int batches = outer * inner;
    if (M % 128 == 0 && M > 128) {
        if (!transB && (N % 128) == 0) {
            dim3 grid(N / 128, M / 128, batches);
            tgemm_kernel<128, 128, 256><<<grid, 256>>>(A, B, bias, C, K, lda, ldb, ldc,
                                                       sAo, sAi, sBo, sBi, sCo, sCi,
                                                       inner, alpha, 0);
        } else {
            dim3 grid(N / 64, M / 128, batches);
            tgemm_kernel<128, 64, 256><<<grid, 256>>>(A, B, bias, C, K, lda, ldb, ldc,
                                                      sAo, sAi, sBo, sBi, sCo, sCi,
                                                      inner, alpha, transB);
        }
    } else {
        dim3 grid(N / 64, M / 64, batches);
        tgemm_kernel<64, 64, 128><<<grid, 128>>>(A, B, bias, C, K, lda, ldb, ldc,
                                                 sAo, sAi, sBo, sBi, sCo, sCi,
                                                 inner, alpha, transB);
    }
}

extern "C" void kernel_launch(void* const* d_in, const int* in_sizes, int n_in,
                              void* d_out, int out_size)
{
    const float* q         = (const float*)d_in[0];
    const float* kv        = (const float*)d_in[1];
    const float* Wq        = (const float*)d_in[2];
    const float* Wkv       = (const float*)d_in[3];
    const float* Wproj     = (const float*)d_in[4];
    const float* bproj     = (const float*)d_in[5];
    const float* Wp_w      = (const float*)d_in[6];
    const float* Wp_b      = (const float*)d_in[7];
    const float* vp_w      = (const float*)d_in[8];
    const float* vp_b      = (const float*)d_in[9];
    const float* Wqpos     = (const float*)d_in[10];
    const float* bqpos     = (const float*)d_in[11];
    const float* Wrctc     = (const float*)d_in[12];
    const float* brctc     = (const float*)d_in[13];
    const float* ca1_Wq    = (const float*)d_in[14];
    const float* ca1_Wkv   = (const float*)d_in[15];
    const float* ca1_Wproj = (const float*)d_in[16];
    const float* ca1_bproj = (const float*)d_in[17];
    const float* ca2_Wq    = (const float*)d_in[18];
    const float* ca2_Wkv   = (const float*)d_in[19];
    const float* ca2_Wproj = (const float*)d_in[20];
    const float* ca2_bproj = (const float*)d_in[21];
    const float* g_q1      = (const float*)d_in[22];
    const float* b_q1      = (const float*)d_in[23];
    const float* g_kv1     = (const float*)d_in[24];
    const float* b_kv1     = (const float*)d_in[25];
    const float* g_q2      = (const float*)d_in[26];
    const float* b_q2      = (const float*)d_in[27];
    const float* g_kv2     = (const float*)d_in[28];
    const float* b_kv2     = (const float*)d_in[29];
    float* out = (float*)d_out;

    float* scr = nullptr;
    cudaGetSymbolAddress((void**)&scr, SCR);

    float* decm   = scr + OFF_DECM;
    float* dec    = scr + OFF_DEC;
    float* lndec  = scr + OFF_LNDEC;
    float* kvmain = scr + OFF_KVMAIN;
    float* kv2    = scr + OFF_KV2;
    float* kv1    = scr + OFF_KV1;
    float* qh     = scr + OFF_QH;
    float* p0     = scr + OFF_P0;
    float* lnA    = scr + OFF_LNA;
    float* lnB    = scr + OFF_LNB;
    float* qh1    = scr + OFF_QH1;
    float* x1     = scr + OFF_X1;
    float* p1     = scr + OFF_P1;
    float* qh2    = scr + OFF_QH2;
    float* x2     = scr + OFF_X2;
    float* p2     = scr + OFF_P2;
    float* tbuf   = scr + OFF_TBUF;
    float* xmain  = scr + OFF_XMAIN;
    float* sc1    = scr + OFF_SC1;
    float* sc2    = scr + OFF_SC2;
    float* scm    = scr + OFF_SCM;
    float* pt     = scr + OFF_PT;

    const float scale_main = rsqrtf((float)Cq);   // hd = 384 for nh=1
    const float scale_h    = rsqrtf((float)HD2);  // hd = 192 for nh=2

    // 1. dec mean over H
    mean_h_kernel<<<Bq*Ww/4, 384>>>(kv, decm);

    // 2. dec = decm @ Wrctc + brctc      [B, 512, 384]
    gemm(decm, Wrctc, brctc, dec, Ww, Cq, Cq, Cq, Cq, Cq,
         (long long)Ww*Cq, 0, 0, 0, (long long)Ww*Cq, 0, Bq, 1, 1.0f, 0);

    // 3. qh = (q @ Wq) * scale_main     [B, 128, 384]
    gemm(q, Wq, nullptr, qh, Sq, Cq, Cq, Cq, Cq, Cq,
         (long long)Sq*Cq, 0, 0, 0, (long long)Sq*Cq, 0, Bq, 1, scale_main, 0);

    // 4. kvmain = dec @ Wkv             [B, 512, 768]
    gemm(dec, Wkv, nullptr, kvmain, Ww, 2*Cq, Cq, Cq, 2*Cq, 2*Cq,
         (long long)Ww*Cq, 0, 0, 0, (long long)Ww*2*Cq, 0, Bq, 1, 1.0f, 0);

    // 5. p0 = q @ Wqpos + bqpos
    gemm(q, Wqpos, bqpos, p0, Sq, Cq, Cq, Cq, Cq, Cq,
         (long long)Sq*Cq, 0, 0, 0, (long long)Sq*Cq, 0, Bq, 1, 1.0f, 0);

    // 6/7. LayerNorms for ca1
    ln_kernel<<<Bq*Sq, 128>>>(p0, g_q1, b_q1, lnA);
    ln_kernel<<<Bq*Sq, 128>>>(q,  g_kv1, b_kv1, lnB);

    // 8. qh1 = (lnA @ ca1_Wq) * scale_h
    gemm(lnA, ca1_Wq, nullptr, qh1, Sq, Cq, Cq, Cq, Cq, Cq,
         (long long)Sq*Cq, 0, 0, 0, (long long)Sq*Cq, 0, Bq, 1, scale_h, 0);

    // 9. kv1 = lnB @ ca1_Wkv            [B, 128, 768]
    gemm(lnB, ca1_Wkv, nullptr, kv1, Sq, 2*Cq, Cq, Cq, 2*Cq, 2*Cq,
         (long long)Sq*Cq, 0, 0, 0, (long long)Sq*2*Cq, 0, Bq, 1, 1.0f, 0);

    // 10. sc1[b,h] = qh1_h @ k1_h^T     [B, 2, 128, 128]
    gemm(qh1, kv1, nullptr, sc1, Sq, Sq, HD2, Cq, 2*Cq, Sq,
         (long long)Sq*Cq, HD2, (long long)Sq*2*Cq, HD2,
         (long long)2*Sq*Sq, (long long)Sq*Sq, Bq, 2, 1.0f, 1);

    // 11. softmax over 128 keys
    softmax_kernel<<<Bq*2*Sq, 128>>>(sc1, Sq);

    // 12. x1[b,:,h*192:] = sc1 @ v1_h   [B, 128, 384]
    gemm(sc1, kv1 + Cq, nullptr, x1, Sq, HD2, Sq, Sq, 2*Cq, Cq,
         (long long)2*Sq*Sq, (long long)Sq*Sq, (long long)Sq*2*Cq, HD2,
         (long long)Sq*Cq, HD2, Bq, 2, 1.0f, 0);

    // 13. p1 = x1 @ ca1_Wproj + ca1_bproj
    gemm(x1, ca1_Wproj, ca1_bproj, p1, Sq, Cq, Cq, Cq, Cq, Cq,
         (long long)Sq*Cq, 0, 0, 0, (long long)Sq*Cq, 0, Bq, 1, 1.0f, 0);

    // 14/15. LayerNorms for ca2
    ln_kernel<<<Bq*Sq, 128>>>(p1, g_q2, b_q2, lnA);   // reuse lnA
    ln_kernel<<<Bq*Ww, 128>>>(dec, g_kv2, b_kv2, lndec);

    // 16. qh2 = (lnA @ ca2_Wq) * scale_h
    gemm(lnA, ca2_Wq, nullptr, qh2, Sq, Cq, Cq, Cq, Cq, Cq,
         (long long)Sq*Cq, 0, 0, 0, (long long)Sq*Cq, 0, Bq, 1, scale_h, 0);

    // 17. kv2 = lndec @ ca2_Wkv         [B, 512, 768]
    gemm(lndec, ca2_Wkv, nullptr, kv2, Ww, 2*Cq, Cq, Cq, 2*Cq, 2*Cq,
         (long long)Ww*Cq, 0, 0, 0, (long long)Ww*2*Cq, 0, Bq, 1, 1.0f, 0);

    // 18. sc2[b,h] = qh2_h @ k2_h^T     [B, 2, 128, 512]
    gemm(qh2, kv2, nullptr, sc2, Sq, Ww, HD2, Cq, 2*Cq, Ww,
         (long long)Sq*Cq, HD2, (long long)Ww*2*Cq, HD2,
         (long long)2*Sq*Ww, (long long)Sq*Ww, Bq, 2, 1.0f, 1);

    // 19. softmax over 512 keys
    softmax_kernel<<<Bq*2*Sq, 256>>>(sc2, Ww);

    // 20. x2 = sc2 @ v2_h               [B, 128, 384]
    gemm(sc2, kv2 + Cq, nullptr, x2, Sq, HD2, Ww, Ww, 2*Cq, Cq,
         (long long)2*Sq*Ww, (long long)Sq*Ww, (long long)Ww*2*Cq, HD2,
         (long long)Sq*Cq, HD2, Bq, 2, 1.0f, 0);

    // 21. p2 = x2 @ ca2_Wproj + ca2_bproj
    gemm(x2, ca2_Wproj, ca2_bproj, p2, Sq, Cq, Cq, Cq, Cq, Cq,
         (long long)Sq*Cq, 0, 0, 0, (long long)Sq*Cq, 0, Bq, 1, 1.0f, 0);

    // 22. tbuf = p2 @ Wp_w + Wp_b
    gemm(p2, Wp_w, Wp_b, tbuf, Sq, Cq, Cq, Cq, Cq, Cq,
         (long long)Sq*Cq, 0, 0, 0, (long long)Sq*Cq, 0, Bq, 1, 1.0f, 0);

    // 23. p_t
    pt_kernel<<<Bq*Sq, 128>>>(tbuf, vp_w, vp_b, pt);

    // 24. main scores = qh @ k_main^T   [B, 128, 512]
    gemm(qh, kvmain, nullptr, scm, Sq, Ww, Cq, Cq, 2*Cq, Ww,
         (long long)Sq*Cq, 0, (long long)Ww*2*Cq, 0,
         (long long)Sq*Ww, 0, Bq, 1, 1.0f, 1);

    // 25/26. fused gaussian window + softmax over W
    gauss_softmax_kernel<<<Bq*Sq, 256>>>(scm, pt);

    // 27. xmain = scm @ v_main          [B, 128, 384]
    gemm(scm, kvmain + Cq, nullptr, xmain, Sq, Cq, Ww, Ww, 2*Cq, Cq,
         (long long)Sq*Ww, 0, (long long)Ww*2*Cq, 0,
         (long long)Sq*Cq, 0, Bq, 1, 1.0f, 0);

    // 28. out = xmain @ Wproj + bproj
    gemm(xmain, Wproj, bproj, out, Sq, Cq, Cq, Cq, Cq, Cq,
         (long long)Sq*Cq, 0, 0, 0, (long long)Sq*Cq, 0, Bq, 1, 1.0f, 0);
}

// round 17
// speedup vs baseline: 1.0919x; 1.0678x over previous
#include <cuda_runtime.h>
#include <cuda_bf16.h>
#include <math.h>
#include <stdint.h>

// Problem constants (fixed by setup_inputs)
#define Bq   32
#define Sq   128
#define Cq   384
#define Hh   8
#define Ww   512
#define Nkv  (Hh*Ww)        // 4096
#define HD2  192            // head dim for nh=2 cross-attn
// SIGMA = 3 -> 2*sigma^2 = 18

// ---------------------------------------------------------------------------
// Scratch (single __device__ global; no allocations allowed)
// ---------------------------------------------------------------------------
#define SZ_BWC   (Bq*Ww*Cq)
#define SZ_BW2C  (Bq*Ww*2*Cq)
#define SZ_BSC   (Bq*Sq*Cq)
#define SZ_BS2C  (Bq*Sq*2*Cq)
#define SZ_SC1   (Bq*2*Sq*Sq)
#define SZ_SC2   (Bq*2*Sq*Ww)
#define SZ_SCM   (Bq*Sq*Ww)
#define SZ_PT    (Bq*Sq)

#define OFF_DECM   0
#define OFF_DEC    (OFF_DECM + SZ_BWC)
#define OFF_LNDEC  (OFF_DEC + SZ_BWC)
#define OFF_KVMAIN (OFF_LNDEC + SZ_BWC)
#define OFF_KV2    (OFF_KVMAIN + SZ_BW2C)
#define OFF_KV1    (OFF_KV2 + SZ_BW2C)
#define OFF_QH     (OFF_KV1 + SZ_BS2C)
#define OFF_P0     (OFF_QH   + SZ_BSC)
#define OFF_LNA    (OFF_P0   + SZ_BSC)
#define OFF_LNB    (OFF_LNA  + SZ_BSC)
#define OFF_QH1    (OFF_LNB  + SZ_BSC)
#define OFF_X1     (OFF_QH1  + SZ_BSC)
#define OFF_P1     (OFF_X1   + SZ_BSC)
#define OFF_QH2    (OFF_P1   + SZ_BSC)
#define OFF_X2     (OFF_QH2  + SZ_BSC)
#define OFF_P2     (OFF_X2   + SZ_BSC)
#define OFF_TBUF   (OFF_P2   + SZ_BSC)
#define OFF_XMAIN  (OFF_TBUF + SZ_BSC)
#define OFF_SC1    (OFF_XMAIN+ SZ_BSC)
#define OFF_SC2    (OFF_SC1  + SZ_SC1)
#define OFF_SCM    (OFF_SC2  + SZ_SC2)
#define OFF_PT     (OFF_SCM  + SZ_SCM)
#define SCR_TOTAL  (OFF_PT + SZ_PT)

__device__ float SCR[SCR_TOTAL];

// ---------------------------------------------------------------------------
// Block reductions
// ---------------------------------------------------------------------------
__device__ __forceinline__ float blk_reduce_sum(float v) {
    __shared__ float sh[32];
    int lane = threadIdx.x & 31, w = threadIdx.x >> 5;
    #pragma unroll
    for (int o = 16; o; o >>= 1) v += __shfl_xor_sync(0xffffffffu, v, o);
    __syncthreads();
    if (lane == 0) sh[w] = v;
    __syncthreads();
    int nw = (blockDim.x + 31) >> 5;
    float r = (lane < nw) ? sh[lane] : 0.f;
    #pragma unroll
    for (int o = 16; o; o >>= 1) r += __shfl_xor_sync(0xffffffffu, r, o);
    return r;
}

__device__ __forceinline__ float blk_reduce_max(float v) {
    __shared__ float sh[32];
    int lane = threadIdx.x & 31, w = threadIdx.x >> 5;
    #pragma unroll
    for (int o = 16; o; o >>= 1) v = fmaxf(v, __shfl_xor_sync(0xffffffffu, v, o));
    __syncthreads();
    if (lane == 0) sh[w] = v;
    __syncthreads();
    int nw = (blockDim.x + 31) >> 5;
    float r = (lane < nw) ? sh[lane] : -3.4e38f;
    #pragma unroll
    for (int o = 16; o; o >>= 1) r = fmaxf(r, __shfl_xor_sync(0xffffffffu, r, o));
    return r;
}

// ---------------------------------------------------------------------------
// tf32 helpers
// ---------------------------------------------------------------------------
__device__ __forceinline__ uint32_t f2tf32(float f) {
    uint32_t u;
    asm("cvt.rna.tf32.f32 %0, %1;" : "=r"(u) : "f"(f));
    return u;
}

#define MMA_TF32(c, a, b0_, b1_)                                              \
    asm("mma.sync.aligned.m16n8k8.row.col.f32.tf32.tf32.f32 "                 \
        "{%0,%1,%2,%3}, {%4,%5,%6,%7}, {%8,%9}, {%0,%1,%2,%3};"               \
        : "+f"((c)[0]), "+f"((c)[1]), "+f"((c)[2]), "+f"((c)[3])              \
        : "r"((a)[0]), "r"((a)[1]), "r"((a)[2]), "r"((a)[3]),                 \
          "r"(b0_), "r"(b1_))

#define LDSM_X4(r0, r1, r2, r3, addr)                                         \
    asm volatile("ldmatrix.sync.aligned.m8n8.x4.shared.b16 {%0,%1,%2,%3}, [%4];" \
        : "=r"(r0), "=r"(r1), "=r"(r2), "=r"(r3) : "r"(addr))

// ---------------------------------------------------------------------------
// TF32 tensor-core GEMM: C = alpha * A @ op(B) (+ bias)
// Block BM x BN, THREADS = 2*BM, warp tile 32 x (BN/2),
// mma m16n8k8 (2 M-tiles x BN/16 N-tiles per warp), K-tile 16.
// A smem: row-major [m][16k], stride 20 u32; A fragments via ldmatrix.x4
//   (row starts 20r mod 32 = perfect bank permutation -> conflict-free).
// B smem: [k][n], stride BN+8 (== 8 mod 32) -> scalar fragment loads
//   conflict-free (proven R9).
// BN=128 path (non-trans only): PING-PONG double buffer, one sync per
//   K-tile, STS of tile s+1 overlapped with MMAs of tile s. K/16 must be
//   even (true for all call sites). Other paths: proven single-buffer loop.
// Requirements: M%BM==0, N%BN==0, K%16==0, leading dims %4==0.
// ---------------------------------------------------------------------------
template<int BM, int BN, int THREADS>
__global__ __launch_bounds__(THREADS)
void tgemm_kernel(const float* __restrict__ A, const float* __restrict__ B,
                  const float* __restrict__ bias, float* __restrict__ C,
                  int K, int lda, int ldb, int ldc,
                  long long sAo, long long sAi,
                  long long sBo, long long sBi,
                  long long sCo, long long sCi,
                  int inner, float alpha, int transB)
{
    constexpr int WM_CNT = BM / 32;      // 4 or 2
    constexpr int WNT    = BN / 16;      // N-tiles per warp (4 or 8)
    constexpr int BST    = BN + 8;       // 72 or 136; both == 8 (mod 32)
    constexpr int NBUF   = (BN == 128) ? 2 : 1;
    __shared__ uint32_t As[NBUF][BM][20];   // [buf][m][k], tf32 bits
    __shared__ uint32_t Bs[NBUF][16][BST];  // [buf][k][n], tf32 bits

    int z = blockIdx.z;
    int o = z / inner, ii = z - o * inner;
    A += (long long)o * sAo + (long long)ii * sAi;
    B += (long long)o * sBo + (long long)ii * sBi;
    C += (long long)o * sCo + (long long)ii * sCi;

    const int tid  = threadIdx.x;
    const int lane = tid & 31;
    const int wid  = tid >> 5;
    const int g    = lane >> 2;     // groupID (0..7)
    const int tig  = lane & 3;      // threadID_in_group (0..3)
    const int wm   = wid % WM_CNT;  // warp M index
    const int wn   = wid / WM_CNT;  // warp N index (0..1)
    const int row0 = blockIdx.y * BM;
    const int col0 = blockIdx.x * BN;

    // Global load mappings
    const int am = tid >> 1;               // A row (0..BM-1)
    const int ak = (tid & 1) << 3;         // A k base (0 or 8)

    // ldmatrix per-lane base address for A (buffer 0)
    uint32_t smemA = (uint32_t)__cvta_generic_to_shared(&As[0][0][0]);
    const uint32_t aldBase = smemA +
        (uint32_t)(((wm * 32 + (lane & 7) + ((lane >> 3) & 1) * 8) * 20 +
                    ((lane >> 4) << 2)) * 4);
    constexpr uint32_t ABUFB = (uint32_t)(BM * 20 * 4);  // bytes per A buffer

    float4 pa0, pa1, pb0, pb1;

    auto load_g = [&](int kk) {
        const float* pA = &A[(long long)(row0 + am) * lda + kk + ak];
        pa0 = *(const float4*)pA;  pa1 = *(const float4*)(pA + 4);
        if (BN == 128) {
            int bk = tid >> 4, bn8 = (tid & 15) << 3;
            const float* pB = &B[(long long)(kk + bk) * ldb + col0 + bn8];
            pb0 = *(const float4*)pB;  pb1 = *(const float4*)(pB + 4);
        } else if (!transB) {
            if (THREADS == 256) {
                int bk = tid >> 4, bn4 = (tid & 15) << 2;
                pb0 = *(const float4*)&B[(long long)(kk + bk) * ldb + col0 + bn4];
            } else {
                int bk = tid >> 3, bn8 = (tid & 7) << 3;
                const float* pB = &B[(long long)(kk + bk) * ldb + col0 + bn8];
                pb0 = *(const float4*)pB;  pb1 = *(const float4*)(pB + 4);
            }
        } else {
            if (THREADS == 256) {
                int bn = tid >> 2, bk4 = (tid & 3) << 2;
                pb0 = *(const float4*)&B[(long long)(col0 + bn) * ldb + kk + bk4];
            } else {
                int bn = tid >> 1, bk8 = (tid & 1) << 3;
                const float* pB = &B[(long long)(col0 + bn) * ldb + kk + bk8];
                pb0 = *(const float4*)pB;  pb1 = *(const float4*)(pB + 4);
            }
        }
    };

    auto store_s = [&](int bf) {
        {
            uint4 u0 = make_uint4(f2tf32(pa0.x), f2tf32(pa0.y),
                                  f2tf32(pa0.z), f2tf32(pa0.w));
            uint4 u1 = make_uint4(f2tf32(pa1.x), f2tf32(pa1.y),
                                  f2tf32(pa1.z), f2tf32(pa1.w));
            *(uint4*)&As[bf][am][ak]     = u0;
            *(uint4*)&As[bf][am][ak + 4] = u1;
        }
        if (BN == 128) {
            int bk = tid >> 4, bn8 = (tid & 15) << 3;
            uint4 u0 = make_uint4(f2tf32(pb0.x), f2tf32(pb0.y),
                                  f2tf32(pb0.z), f2tf32(pb0.w));
            uint4 u1 = make_uint4(f2tf32(pb1.x), f2tf32(pb1.y),
                                  f2tf32(pb1.z), f2tf32(pb1.w));
            *(uint4*)&Bs[bf][bk][bn8]     = u0;
            *(uint4*)&Bs[bf][bk][bn8 + 4] = u1;
        } else if (!transB) {
            if (THREADS == 256) {
                int bk = tid >> 4, bn4 = (tid & 15) << 2;
                uint4 u = make_uint4(f2tf32(pb0.x), f2tf32(pb0.y),
                                     f2tf32(pb0.z), f2tf32(pb0.w));
                *(uint4*)&Bs[bf][bk][bn4] = u;
            } else {
                int bk = tid >> 3, bn8 = (tid & 7) << 3;
                uint4 u0 = make_uint4(f2tf32(pb0.x), f2tf32(pb0.y),
                                      f2tf32(pb0.z), f2tf32(pb0.w));
                uint4 u1 = make_uint4(f2tf32(pb1.x), f2tf32(pb1.y),
                                      f2tf32(pb1.z), f2tf32(pb1.w));
                *(uint4*)&Bs[bf][bk][bn8]     = u0;
                *(uint4*)&Bs[bf][bk][bn8 + 4] = u1;
            }
        } else {
            if (THREADS == 256) {
                int bn = tid >> 2, bk4 = (tid & 3) << 2;
                Bs[bf][bk4+0][bn] = f2tf32(pb0.x); Bs[bf][bk4+1][bn] = f2tf32(pb0.y);
                Bs[bf][bk4+2][bn] = f2tf32(pb0.z); Bs[bf][bk4+3][bn] = f2tf32(pb0.w);
            } else {
                int bn = tid >> 1, bk8 = (tid & 1) << 3;
                Bs[bf][bk8+0][bn] = f2tf32(pb0.x); Bs[bf][bk8+1][bn] = f2tf32(pb0.y);
                Bs[bf][bk8+2][bn] = f2tf32(pb0.z); Bs[bf][bk8+3][bn] = f2tf32(pb0.w);
                Bs[bf][bk8+4][bn] = f2tf32(pb1.x); Bs[bf][bk8+5][bn] = f2tf32(pb1.y);
                Bs[bf][bk8+6][bn] = f2tf32(pb1.z); Bs[bf][bk8+7][bn] = f2tf32(pb1.w);
            }
        }
    };

    float acc[2][WNT][4];
    #pragma unroll
    for (int mt = 0; mt < 2; mt++)
        #pragma unroll
        for (int nt = 0; nt < WNT; nt++)
            #pragma unroll
            for (int r = 0; r < 4; r++) acc[mt][nt][r] = 0.f;

    auto compute = [&](int bf) {
        #pragma unroll
        for (int k0 = 0; k0 < 16; k0 += 8) {
            uint32_t a[2][4];
            #pragma unroll
            for (int mt = 0; mt < 2; mt++) {
                LDSM_X4(a[mt][0], a[mt][1], a[mt][2], a[mt][3],
                        aldBase + (uint32_t)bf * ABUFB +
                        (uint32_t)(mt * 1280 + k0 * 4));
            }
            #pragma unroll
            for (int nt = 0; nt < WNT; nt++) {
                int nbase = wn * (BN/2) + nt * 8 + g;
                uint32_t b0 = Bs[bf][k0 + tig    ][nbase];
                uint32_t b1 = Bs[bf][k0 + tig + 4][nbase];
                MMA_TF32(acc[0][nt], a[0], b0, b1);
                MMA_TF32(acc[1][nt], a[1], b0, b1);
            }
        }
    };

    if (NBUF == 2) {
        // ping-pong: one sync per K-tile; K/16 even at all call sites
        load_g(0);
        store_s(0);
        __syncthreads();
        for (int kk = 0; kk < K; kk += 32) {
            if (kk + 16 < K) load_g(kk + 16);
            compute(0);
            if (kk + 16 < K) store_s(1);
            __syncthreads();
            if (kk + 16 >= K) break;
            if (kk + 32 < K) load_g(kk + 32);
            compute(1);
            if (kk + 32 < K) store_s(0);
            __syncthreads();
        }
    } else {
        load_g(0);
        for (int kk = 0; kk < K; kk += 16) {
            __syncthreads();
            store_s(0);
            __syncthreads();
            if (kk + 16 < K) load_g(kk + 16);
            compute(0);
        }
    }

    // Epilogue
    #pragma unroll
    for (int mt = 0; mt < 2; mt++) {
        int r0 = row0 + wm * 32 + mt * 16 + g;
        #pragma unroll
        for (int nt = 0; nt < WNT; nt++) {
            int cc = col0 + wn * (BN/2) + nt * 8 + (tig << 1);
            float b0 = 0.f, b1 = 0.f;
            if (bias) { b0 = bias[cc]; b1 = bias[cc + 1]; }
            float2 v0, v1;
            v0.x = fmaf(acc[mt][nt][0], alpha, b0);
            v0.y = fmaf(acc[mt][nt][1], alpha, b1);
            v1.x = fmaf(acc[mt][nt][2], alpha, b0);
            v1.y = fmaf(acc[mt][nt][3], alpha, b1);
            *(float2*)&C[(long long)r0 * ldc + cc]       = v0;
            *(float2*)&C[(long long)(r0 + 8) * ldc + cc] = v1;
        }
    }
}

// ---------------------------------------------------------------------------
// dec mean over H (float4):  decm[b,w,c] = mean_h kv[b, h*W + w, c]
// ---------------------------------------------------------------------------
__global__ void mean_h_kernel(const float* __restrict__ kv, float* __restrict__ out)
{
    int blk = blockIdx.x;              // 0 .. Bq*Ww/4-1
    int b  = blk / (Ww/4);
    int w4 = blk - b * (Ww/4);
    int wl = threadIdx.x / 96;         // 0..3
    int c4 = threadIdx.x % 96;         // float4 index
    int w = w4 * 4 + wl;
    float4 s = make_float4(0.f,0.f,0.f,0.f);
    #pragma unroll
    for (int h = 0; h < Hh; h++) {
        const float4 v = *(const float4*)&kv[((long long)(b*Nkv + h*Ww + w)) * Cq + c4*4];
        s.x += v.x; s.y += v.y; s.z += v.z; s.w += v.w;
    }
    const float inv = 1.0f / Hh;
    s.x *= inv; s.y *= inv; s.z *= inv; s.w *= inv;
    *(float4*)&out[((long long)(b*Ww + w)) * Cq + c4*4] = s;
}

// ---------------------------------------------------------------------------
// LayerNorm over C=384 (128 threads, 3 elems/thread)
// ---------------------------------------------------------------------------
__global__ void ln_kernel(const float* __restrict__ x, const float* __restrict__ g,
                          const float* __restrict__ b, float* __restrict__ y)
{
    long long row = blockIdx.x;
    const float* px = x + row * Cq;
    float* py = y + row * Cq;
    float v[3]; float s = 0.f;
    #pragma unroll
    for (int j = 0; j < 3; j++) { v[j] = px[threadIdx.x + j*128]; s += v[j]; }
    float mean = blk_reduce_sum(s) * (1.0f / Cq);
    float sq = 0.f;
    #pragma unroll
    for (int j = 0; j < 3; j++) { float d = v[j] - mean; sq += d*d; }
    float var = blk_reduce_sum(sq) * (1.0f / Cq);
    float rstd = rsqrtf(var + 1e-6f);
    #pragma unroll
    for (int j = 0; j < 3; j++) {
        int c = threadIdx.x + j*128;
        py[c] = (v[j] - mean) * rstd * g[c] + b[c];
    }
}

// ---------------------------------------------------------------------------
// Row softmax (in place), row length L
// ---------------------------------------------------------------------------
__global__ void softmax_kernel(float* __restrict__ x, int L)
{
    long long row = blockIdx.x;
    float* p = x + row * (long long)L;
    float m = -3.4e38f;
    for (int i = threadIdx.x; i < L; i += blockDim.x) m = fmaxf(m, p[i]);
    m = blk_reduce_max(m);
    float s = 0.f;
    for (int i = threadIdx.x; i < L; i += blockDim.x) {
        float e = expf(p[i] - m); p[i] = e; s += e;
    }
    s = blk_reduce_sum(s);
    float inv = 1.0f / s;
    for (int i = threadIdx.x; i < L; i += blockDim.x) p[i] *= inv;
}

// ---------------------------------------------------------------------------
// Fused gaussian-window + softmax over W=512 (in place). 256 threads.
// ---------------------------------------------------------------------------
__global__ void gauss_softmax_kernel(float* __restrict__ x, const float* __restrict__ pt)
{
    long long row = blockIdx.x;
    float* p = x + row * (long long)Ww;
    const float c = pt[row];
    float v[2];
    #pragma unroll
    for (int j = 0; j < 2; j++) {
        int i = threadIdx.x + j*256;
        float d = (float)i - c;
        v[j] = p[i] * expf(-d*d * (1.0f/18.0f));
    }
    float m = fmaxf(v[0], v[1]);
    m = blk_reduce_max(m);
    float s = 0.f;
    #pragma unroll
    for (int j = 0; j < 2; j++) { v[j] = expf(v[j] - m); s += v[j]; }
    s = blk_reduce_sum(s);
    float inv = 1.0f / s;
    #pragma unroll
    for (int j = 0; j < 2; j++) p[threadIdx.x + j*256] = v[j] * inv;
}

// ---------------------------------------------------------------------------
// p_t[row] = sigmoid( sum_c tanh(tbuf[row,c]) * vp_w[c] + vp_b ) * W
// ---------------------------------------------------------------------------
__global__ void pt_kernel(const float* __restrict__ t, const float* __restrict__ vw,
                          const float* __restrict__ vb, float* __restrict__ pt)
{
    long long row = blockIdx.x;
    float s = 0.f;
    for (int c = threadIdx.x; c < Cq; c += blockDim.x)
        s += tanhf(t[row*Cq + c]) * vw[c];
    s = blk_reduce_sum(s);
    if (threadIdx.x == 0)
        pt[row] = (float)Ww / (1.0f + expf(-(s + vb[0])));
}

// ---------------------------------------------------------------------------
// Host launcher
// ---------------------------------------------------------------------------
static void gemm(const float* A, const float* B, const float* bias, float* C,
                 int M, int N, int K, int lda, int ldb, int ldc,
                 long long sAo, long long sAi, long long sBo, long long sBi,
                 long long sCo, long long sCi, int outer, int inner,
                 float alpha, int transB)
{
    int batches = outer * inner;
    if (M % 128 == 0 && M > 128) {
        if (!transB && (N % 128) == 0) {
            dim3 grid(N / 128, M / 128, batches);
            tgemm_kernel<128, 128, 256><<<grid, 256>>>(A, B, bias, C, K, lda, ldb, ldc,
                                                       sAo, sAi, sBo, sBi, sCo, sCi,
                                                       inner, alpha, 0);
        } else {
            dim3 grid(N / 64, M / 128, batches);
            tgemm_kernel<128, 64, 256><<<grid, 256>>>(A, B, bias, C, K, lda, ldb, ldc,
                                                      sAo, sAi, sBo, sBi, sCo, sCi,
                                                      inner, alpha, transB);
        }
    } else {
        dim3 grid(N / 64, M / 64, batches);
        tgemm_kernel<64, 64, 128><<<grid, 128>>>(A, B, bias, C, K, lda, ldb, ldc,
                                                 sAo, sAi, sBo, sBi, sCo, sCi,
                                                 inner, alpha, transB);
    }
}

extern "C" void kernel_launch(void* const* d_in, const int* in_sizes, int n_in,
                              void* d_out, int out_size)
{
    const float* q         = (const float*)d_in[0];
    const float* kv        = (const float*)d_in[1];
    const float* Wq        = (const float*)d_in[2];
    const float* Wkv       = (const float*)d_in[3];
    const float* Wproj     = (const float*)d_in[4];
    const float* bproj     = (const float*)d_in[5];
    const float* Wp_w      = (const float*)d_in[6];
    const float* Wp_b      = (const float*)d_in[7];
    const float* vp_w      = (const float*)d_in[8];
    const float* vp_b      = (const float*)d_in[9];
    const float* Wqpos     = (const float*)d_in[10];
    const float* bqpos     = (const float*)d_in[11];
    const float* Wrctc     = (const float*)d_in[12];
    const float* brctc     = (const float*)d_in[13];
    const float* ca1_Wq    = (const float*)d_in[14];
    const float* ca1_Wkv   = (const float*)d_in[15];
    const float* ca1_Wproj = (const float*)d_in[16];
    const float* ca1_bproj = (const float*)d_in[17];
    const float* ca2_Wq    = (const float*)d_in[18];
    const float* ca2_Wkv   = (const float*)d_in[19];
    const float* ca2_Wproj = (const float*)d_in[20];
    const float* ca2_bproj = (const float*)d_in[21];
    const float* g_q1      = (const float*)d_in[22];
    const float* b_q1      = (const float*)d_in[23];
    const float* g_kv1     = (const float*)d_in[24];
    const float* b_kv1     = (const float*)d_in[25];
    const float* g_q2      = (const float*)d_in[26];
    const float* b_q2      = (const float*)d_in[27];
    const float* g_kv2     = (const float*)d_in[28];
    const float* b_kv2     = (const float*)d_in[29];
    float* out = (float*)d_out;

    float* scr = nullptr;
    cudaGetSymbolAddress((void**)&scr, SCR);

    float* decm   = scr + OFF_DECM;
    float* dec    = scr + OFF_DEC;
    float* lndec  = scr + OFF_LNDEC;
    float* kvmain = scr + OFF_KVMAIN;
    float* kv2    = scr + OFF_KV2;
    float* kv1    = scr + OFF_KV1;
    float* qh     = scr + OFF_QH;
    float* p0     = scr + OFF_P0;
    float* lnA    = scr + OFF_LNA;
    float* lnB    = scr + OFF_LNB;
    float* qh1    = scr + OFF_QH1;
    float* x1     = scr + OFF_X1;
    float* p1     = scr + OFF_P1;
    float* qh2    = scr + OFF_QH2;
    float* x2     = scr + OFF_X2;
    float* p2     = scr + OFF_P2;
    float* tbuf   = scr + OFF_TBUF;
    float* xmain  = scr + OFF_XMAIN;
    float* sc1    = scr + OFF_SC1;
    float* sc2    = scr + OFF_SC2;
    float* scm    = scr + OFF_SCM;
    float* pt     = scr + OFF_PT;

    const float scale_main = rsqrtf((float)Cq);   // hd = 384 for nh=1
    const float scale_h    = rsqrtf((float)HD2);  // hd = 192 for nh=2

    // 1. dec mean over H
    mean_h_kernel<<<Bq*Ww/4, 384>>>(kv, decm);

    // 2. dec = decm @ Wrctc + brctc      [B, 512, 384]
    gemm(decm, Wrctc, brctc, dec, Ww, Cq, Cq, Cq, Cq, Cq,
         (long long)Ww*Cq, 0, 0, 0, (long long)Ww*Cq, 0, Bq, 1, 1.0f, 0);

    // 3. qh = (q @ Wq) * scale_main     [B, 128, 384]
    gemm(q, Wq, nullptr, qh, Sq, Cq, Cq, Cq, Cq, Cq,
         (long long)Sq*Cq, 0, 0, 0, (long long)Sq*Cq, 0, Bq, 1, scale_main, 0);

    // 4. kvmain = dec @ Wkv             [B, 512, 768]
    gemm(dec, Wkv, nullptr, kvmain, Ww, 2*Cq, Cq, Cq, 2*Cq, 2*Cq,
         (long long)Ww*Cq, 0, 0, 0, (long long)Ww*2*Cq, 0, Bq, 1, 1.0f, 0);

    // 5. p0 = q @ Wqpos + bqpos
    gemm(q, Wqpos, bqpos, p0, Sq, Cq, Cq, Cq, Cq, Cq,
         (long long)Sq*Cq, 0, 0, 0, (long long)Sq*Cq, 0, Bq, 1, 1.0f, 0);

    // 6/7. LayerNorms for ca1
    ln_kernel<<<Bq*Sq, 128>>>(p0, g_q1, b_q1, lnA);
    ln_kernel<<<Bq*Sq, 128>>>(q,  g_kv1, b_kv1, lnB);

    // 8. qh1 = (lnA @ ca1_Wq) * scale_h
    gemm(lnA, ca1_Wq, nullptr, qh1, Sq, Cq, Cq, Cq, Cq, Cq,
         (long long)Sq*Cq, 0, 0, 0, (long long)Sq*Cq, 0, Bq, 1, scale_h, 0);

    // 9. kv1 = lnB @ ca1_Wkv            [B, 128, 768]
    gemm(lnB, ca1_Wkv, nullptr, kv1, Sq, 2*Cq, Cq, Cq, 2*Cq, 2*Cq,
         (long long)Sq*Cq, 0, 0, 0, (long long)Sq*2*Cq, 0, Bq, 1, 1.0f, 0);

    // 10. sc1[b,h] = qh1_h @ k1_h^T     [B, 2, 128, 128]
    gemm(qh1, kv1, nullptr, sc1, Sq, Sq, HD2, Cq, 2*Cq, Sq,
         (long long)Sq*Cq, HD2, (long long)Sq*2*Cq, HD2,
         (long long)2*Sq*Sq, (long long)Sq*Sq, Bq, 2, 1.0f, 1);

    // 11. softmax over 128 keys
    softmax_kernel<<<Bq*2*Sq, 128>>>(sc1, Sq);

    // 12. x1[b,:,h*192:] = sc1 @ v1_h   [B, 128, 384]
    gemm(sc1, kv1 + Cq, nullptr, x1, Sq, HD2, Sq, Sq, 2*Cq, Cq,
         (long long)2*Sq*Sq, (long long)Sq*Sq, (long long)Sq*2*Cq, HD2,
         (long long)Sq*Cq, HD2, Bq, 2, 1.0f, 0);

    // 13. p1 = x1 @ ca1_Wproj + ca1_bproj
    gemm(x1, ca1_Wproj, ca1_bproj, p1, Sq, Cq, Cq, Cq, Cq, Cq,
         (long long)Sq*Cq, 0, 0, 0, (long long)Sq*Cq, 0, Bq, 1, 1.0f, 0);

    // 14/15. LayerNorms for ca2
    ln_kernel<<<Bq*Sq, 128>>>(p1, g_q2, b_q2, lnA);   // reuse lnA
    ln_kernel<<<Bq*Ww, 128>>>(dec, g_kv2, b_kv2, lndec);

    // 16. qh2 = (lnA @ ca2_Wq) * scale_h
    gemm(lnA, ca2_Wq, nullptr, qh2, Sq, Cq, Cq, Cq, Cq, Cq,
         (long long)Sq*Cq, 0, 0, 0, (long long)Sq*Cq, 0, Bq, 1, scale_h, 0);

    // 17. kv2 = lndec @ ca2_Wkv         [B, 512, 768]
    gemm(lndec, ca2_Wkv, nullptr, kv2, Ww, 2*Cq, Cq, Cq, 2*Cq, 2*Cq,
         (long long)Ww*Cq, 0, 0, 0, (long long)Ww*2*Cq, 0, Bq, 1, 1.0f, 0);

    // 18. sc2[b,h] = qh2_h @ k2_h^T     [B, 2, 128, 512]
    gemm(qh2, kv2, nullptr, sc2, Sq, Ww, HD2, Cq, 2*Cq, Ww,
         (long long)Sq*Cq, HD2, (long long)Ww*2*Cq, HD2,
         (long long)2*Sq*Ww, (long long)Sq*Ww, Bq, 2, 1.0f, 1);

    // 19. softmax over 512 keys
    softmax_kernel<<<Bq*2*Sq, 256>>>(sc2, Ww);

    // 20. x2 = sc2 @ v2_h               [B, 128, 384]
    gemm(sc2, kv2 + Cq, nullptr, x2, Sq, HD2, Ww, Ww, 2*Cq, Cq,
         (long long)2*Sq*Ww, (long long)Sq*Ww, (long long)Ww*2*Cq, HD2,
         (long long)Sq*Cq, HD2, Bq, 2, 1.0f, 0);

    // 21. p2 = x2 @ ca2_Wproj + ca2_bproj
    gemm(x2, ca2_Wproj, ca2_bproj, p2, Sq, Cq, Cq, Cq, Cq, Cq,
         (long long)Sq*Cq, 0, 0, 0, (long long)Sq*Cq, 0, Bq, 1, 1.0f, 0);

    // 22. tbuf = p2 @ Wp_w + Wp_b
    gemm(p2, Wp_w, Wp_b, tbuf, Sq, Cq, Cq, Cq, Cq, Cq,
         (long long)Sq*Cq, 0, 0, 0, (long long)Sq*Cq, 0, Bq, 1, 1.0f, 0);

    // 23. p_t
    pt_kernel<<<Bq*Sq, 128>>>(tbuf, vp_w, vp_b, pt);

    // 24. main scores = qh @ k_main^T   [B, 128, 512]
    gemm(qh, kvmain, nullptr, scm, Sq, Ww, Cq, Cq, 2*Cq, Ww,
         (long long)Sq*Cq, 0, (long long)Ww*2*Cq, 0,
         (long long)Sq*Ww, 0, Bq, 1, 1.0f, 1);

    // 25/26. fused gaussian window + softmax over W
    gauss_softmax_kernel<<<Bq*Sq, 256>>>(scm, pt);

    // 27. xmain = scm @ v_main          [B, 128, 384]
    gemm(scm, kvmain + Cq, nullptr, xmain, Sq, Cq, Ww, Ww, 2*Cq, Cq,
         (long long)Sq*Ww, 0, (long long)Ww*2*Cq, 0,
         (long long)Sq*Cq, 0, Bq, 1, 1.0f, 0);

    // 28. out = xmain @ Wproj + bproj
    gemm(xmain, Wproj, bproj, out, Sq, Cq, Cq, Cq, Cq, Cq,
         (long long)Sq*Cq, 0, 0, 0, (long long)Sq*Cq, 0, Bq, 1, 1.0f, 0);
}